// round 14
// baseline (speedup 1.0000x reference)
#include <cuda_runtime.h>
#include <cuda_bf16.h>
#include <math.h>
#include <stdint.h>

#define Nn 8192
#define Dd 768
#define H1s 512
#define H2s 256
#define KK 5

typedef unsigned long long ull;
typedef __nv_bfloat16 bf16;
typedef __nv_bfloat162 bf162;

// ---------------- scratch (device globals; no allocation allowed) ----------
__device__ float g_Ab[67108864];            // blended score matrix (N x N)
__device__ float g_L2[Nn * H2s];            // fp32 (head_tail input)
__device__ float g_G[Nn];
__device__ int   g_top[Nn * KK];
__device__ float g_rowsum[Nn];
__device__ unsigned int g_mask[Nn * 256];

__device__ bf16 g_Xh[Nn * Dd],  g_Xl[Nn * Dd];
__device__ bf16 g_Yh[Nn * Dd],  g_Yl[Nn * Dd];
__device__ bf16 g_L1h[Nn * H1s], g_L1l[Nn * H1s];
__device__ bf16 g_Xph[Nn * Dd], g_Xpl[Nn * Dd];
__device__ bf16 g_Aggh[Nn * Dd], g_Aggl[Nn * Dd];
__device__ bf16 g_WgmTh[Dd * Dd], g_WgmTl[Dd * Dd];
__device__ bf16 g_W1aTh[H1s * Dd], g_W1aTl[H1s * Dd];
__device__ bf16 g_W2aTh[H2s * H1s], g_W2aTl[H2s * H1s];
__device__ bf16 g_GcnTh[Dd * Dd], g_GcnTl[Dd * Dd];
__device__ bf16 g_W1bTh[H1s * Dd], g_W1bTl[H1s * Dd];
__device__ bf16 g_W2bTh[H2s * H1s], g_W2bTl[H2s * H1s];

// ---------------- math helpers ---------------------------------------------
__device__ __forceinline__ float geluf(float x) {
    return 0.5f * x * (1.0f + erff(x * 0.70710678118654752f));
}
__device__ __forceinline__ float softplusf(float x) {
    return fmaxf(x, 0.0f) + log1pf(expf(-fabsf(x)));
}
__device__ __forceinline__ float sigmoidf(float x) {
    return 1.0f / (1.0f + expf(-x));
}

// ---------------- HMMA m16n8k16 bf16 wrapper ---------------------------------
__device__ __forceinline__ void mma16816(float* d, const uint32_t* a, const uint32_t* b) {
    asm volatile(
        "mma.sync.aligned.m16n8k16.row.col.f32.bf16.bf16.f32 "
        "{%0,%1,%2,%3}, {%4,%5,%6,%7}, {%8,%9}, {%0,%1,%2,%3};"
        : "+f"(d[0]), "+f"(d[1]), "+f"(d[2]), "+f"(d[3])
        : "r"(a[0]), "r"(a[1]), "r"(a[2]), "r"(a[3]), "r"(b[0]), "r"(b[1]));
}
__device__ __forceinline__ uint32_t smem_to_u32(const void* p) {
    uint32_t a;
    asm("{ .reg .u64 t; cvta.to.shared.u64 t, %1; cvt.u32.u64 %0, t; }"
        : "=r"(a) : "l"(p));
    return a;
}
__device__ __forceinline__ void cp_async16(uint32_t dst, const void* src) {
    asm volatile("cp.async.cg.shared.global [%0], [%1], 16;"
                 :: "r"(dst), "l"(src) : "memory");
}
#define CP_COMMIT() asm volatile("cp.async.commit_group;" ::: "memory")
#define CP_WAIT(n)  asm volatile("cp.async.wait_group %0;" :: "n"(n) : "memory")

__device__ __forceinline__ void write_split(bf16* Ch, bf16* Cl, size_t idx,
                                            float v0, float v1) {
    bf16 h0 = __float2bfloat16_rn(v0);
    bf16 h1 = __float2bfloat16_rn(v1);
    bf162 hh; hh.x = h0; hh.y = h1;
    *reinterpret_cast<bf162*>(Ch + idx) = hh;
    bf162 ll;
    ll.x = __float2bfloat16_rn(v0 - __bfloat162float(h0));
    ll.y = __float2bfloat16_rn(v1 - __bfloat162float(h1));
    *reinterpret_cast<bf162*>(Cl + idx) = ll;
}

// ---------------- bf16 split of a fp32 matrix --------------------------------
__global__ void k_split(const float* __restrict__ src,
                        bf16* __restrict__ hi, bf16* __restrict__ lo, size_t total)
{
    size_t idx = (size_t)blockIdx.x * blockDim.x + threadIdx.x;
    size_t stride = (size_t)gridDim.x * blockDim.x;
    for (size_t p = idx; p < total; p += stride) {
        float v = src[p];
        bf16 h = __float2bfloat16_rn(v);
        hi[p] = h;
        lo[p] = __float2bfloat16_rn(v - __bfloat162float(h));
    }
}

// ---------------- transpose + bf16 split of weight: wT[n][k] = w[k][n] ------
__global__ void k_tsplit(const float* __restrict__ w,
                         bf16* __restrict__ th, bf16* __restrict__ tl,
                         int K, int N)
{
    __shared__ float t[32][33];
    const int bx = blockIdx.x * 32;   // along N
    const int by = blockIdx.y * 32;   // along K
    #pragma unroll
    for (int dy = 0; dy < 32; dy += 8)
        t[threadIdx.y + dy][threadIdx.x] =
            w[(size_t)(by + threadIdx.y + dy) * N + bx + threadIdx.x];
    __syncthreads();
    #pragma unroll
    for (int dy = 0; dy < 32; dy += 8) {
        float v = t[threadIdx.x][threadIdx.y + dy];
        size_t o = (size_t)(bx + threadIdx.y + dy) * K + by + threadIdx.x;
        bf16 h = __float2bfloat16_rn(v);
        th[o] = h;
        tl[o] = __float2bfloat16_rn(v - __bfloat162float(h));
    }
}

// ---------------- unified HMMA NT GEMM (bf16 3-term split, fp32 accum) ------
// 128x128 tile/CTA, 16 warps of 32x32, K chunks of 64, 3-stage cp.async
// pipeline with ONE sync per chunk (R13 structure, verified).
// EP 0: Cf = al*Aecfp + (1-al)*relu(acc)   [streaming stores/loads]
// EP 1: split(gelu(acc + bias))                          (L1)
// EP 2: Cf = gelu(acc + bias)                            (L2, fp32)
// EP 3: split(resid + gelu(acc/max(rowsum,1e-8) + bias)) (gcn -> Xp)
// EP 4: split(acc)                                       (Y)
#define SP 72
#define TILE_E (128 * SP)
#define BUF_E (4 * TILE_E)
#define NSTAGE 3
#define S_SMEM_BYTES (NSTAGE * BUF_E * 2)
#define GT 512
template <int EP>
__global__ void __launch_bounds__(GT, 1) k_hmma(
    const bf16* __restrict__ Ah, const bf16* __restrict__ Al,
    const bf16* __restrict__ Bh, const bf16* __restrict__ Bl,
    float* __restrict__ Cf, bf16* __restrict__ Ch, bf16* __restrict__ Cl,
    int Nc, int Kc,
    const float* __restrict__ bias,
    const float* __restrict__ rowsum,
    const float* __restrict__ resid,
    const float* __restrict__ Aecfp,
    const float* __restrict__ ra)
{
    extern __shared__ bf16 sm[];
    const int tid = threadIdx.x;
    const int wid = tid >> 5;
    const int lane = tid & 31;
    const int g = lane >> 2;
    const int t = lane & 3;
    const int bm = blockIdx.y * 128;
    const int bn = blockIdx.x * 128;
    const int m0 = (wid & 3) * 32;     // warp M block
    const int n0 = (wid >> 2) * 32;    // warp N block

    const uint32_t smem_u32 = smem_to_u32(sm);

    float d[2][4][4];
    #pragma unroll
    for (int i = 0; i < 2; i++)
        #pragma unroll
        for (int j = 0; j < 4; j++)
            #pragma unroll
            for (int e = 0; e < 4; e++) d[i][j][e] = 0.0f;

    const int lrow = tid >> 2;         // 0..127
    const int lq   = tid & 3;          // quarter of 128B row (32B each)

    auto issue_load = [&](int buf, int kc) {
        const size_t gAoff = (size_t)(bm + lrow) * Kc + kc * 64 + lq * 16;
        const size_t gBoff = (size_t)(bn + lrow) * Kc + kc * 64 + lq * 16;
        const uint32_t soff = (buf * BUF_E + lrow * SP + lq * 16) * 2;   // bytes
        #pragma unroll
        for (int q = 0; q < 2; q++) {
            cp_async16(smem_u32 + soff + q * 16,              Ah + gAoff + q * 8);
            cp_async16(smem_u32 + soff + TILE_E * 2 + q * 16, Al + gAoff + q * 8);
            cp_async16(smem_u32 + soff + TILE_E * 4 + q * 16, Bh + gBoff + q * 8);
            cp_async16(smem_u32 + soff + TILE_E * 6 + q * 16, Bl + gBoff + q * 8);
        }
        CP_COMMIT();
    };

    const int NCHUNK = Kc / 64;
    issue_load(0, 0);
    issue_load(1, 1);

    for (int kc = 0; kc < NCHUNK; kc++) {
        if (kc + 1 < NCHUNK) { CP_WAIT(1); }
        else                 { CP_WAIT(0); }
        __syncthreads();

        const int buf = kc % NSTAGE;
        const bf16* sAh = sm + buf * BUF_E;
        const bf16* sAl = sAh + TILE_E;
        const bf16* sBh = sAl + TILE_E;
        const bf16* sBl = sBh + TILE_E;

        #pragma unroll
        for (int ks = 0; ks < 4; ks++) {
            const int k0 = ks * 16;
            uint32_t ah[2][4], al2[2][4], bh[4][2], bl[4][2];
            #pragma unroll
            for (int ma = 0; ma < 2; ma++) {
                int r = m0 + ma * 16 + g;
                int c = k0 + t * 2;
                ah[ma][0] = *(const uint32_t*)&sAh[r * SP + c];
                ah[ma][1] = *(const uint32_t*)&sAh[(r + 8) * SP + c];
                ah[ma][2] = *(const uint32_t*)&sAh[r * SP + c + 8];
                ah[ma][3] = *(const uint32_t*)&sAh[(r + 8) * SP + c + 8];
                al2[ma][0] = *(const uint32_t*)&sAl[r * SP + c];
                al2[ma][1] = *(const uint32_t*)&sAl[(r + 8) * SP + c];
                al2[ma][2] = *(const uint32_t*)&sAl[r * SP + c + 8];
                al2[ma][3] = *(const uint32_t*)&sAl[(r + 8) * SP + c + 8];
            }
            #pragma unroll
            for (int na = 0; na < 4; na++) {
                int n = n0 + na * 8 + g;
                bh[na][0] = *(const uint32_t*)&sBh[n * SP + k0 + t * 2];
                bh[na][1] = *(const uint32_t*)&sBh[n * SP + k0 + 8 + t * 2];
                bl[na][0] = *(const uint32_t*)&sBl[n * SP + k0 + t * 2];
                bl[na][1] = *(const uint32_t*)&sBl[n * SP + k0 + 8 + t * 2];
            }
            #pragma unroll
            for (int ma = 0; ma < 2; ma++)
                #pragma unroll
                for (int na = 0; na < 4; na++)
                    mma16816(d[ma][na], ah[ma], bh[na]);
            #pragma unroll
            for (int ma = 0; ma < 2; ma++)
                #pragma unroll
                for (int na = 0; na < 4; na++)
                    mma16816(d[ma][na], ah[ma], bl[na]);
            #pragma unroll
            for (int ma = 0; ma < 2; ma++)
                #pragma unroll
                for (int na = 0; na < 4; na++)
                    mma16816(d[ma][na], al2[ma], bh[na]);
        }

        if (kc + 2 < NCHUNK) issue_load((kc + 2) % NSTAGE, kc + 2);
    }

    // ---- epilogue
    float alv = 0.f, om = 0.f;
    if (EP == 0) { alv = sigmoidf(*ra); om = __fsub_rn(1.0f, alv); }

    #pragma unroll
    for (int ma = 0; ma < 2; ma++) {
        #pragma unroll
        for (int na = 0; na < 4; na++) {
            const int r = bm + m0 + ma * 16 + g;
            const int c = bn + n0 + na * 8 + t * 2;
            const size_t i0 = (size_t)r * Nc + c;
            const size_t i1 = (size_t)(r + 8) * Nc + c;
            float v0 = d[ma][na][0], v1 = d[ma][na][1];
            float v2 = d[ma][na][2], v3 = d[ma][na][3];

            if (EP == 0) {
                // streaming loads/stores: keep split operands resident in L2
                float2 a0 = __ldcs(reinterpret_cast<const float2*>(&Aecfp[i0]));
                float2 a1 = __ldcs(reinterpret_cast<const float2*>(&Aecfp[i1]));
                float2 o0, o1;
                o0.x = __fadd_rn(__fmul_rn(alv, a0.x), __fmul_rn(om, fmaxf(v0, 0.0f)));
                o0.y = __fadd_rn(__fmul_rn(alv, a0.y), __fmul_rn(om, fmaxf(v1, 0.0f)));
                o1.x = __fadd_rn(__fmul_rn(alv, a1.x), __fmul_rn(om, fmaxf(v2, 0.0f)));
                o1.y = __fadd_rn(__fmul_rn(alv, a1.y), __fmul_rn(om, fmaxf(v3, 0.0f)));
                __stcs(reinterpret_cast<float2*>(&Cf[i0]), o0);
                __stcs(reinterpret_cast<float2*>(&Cf[i1]), o1);
            } else if (EP == 4) {
                write_split(Ch, Cl, i0, v0, v1);
                write_split(Ch, Cl, i1, v2, v3);
            } else {
                const float b0 = bias[c], b1 = bias[c + 1];
                if (EP == 3) {
                    float rs0 = 1.0f / fmaxf(rowsum[r], 1e-8f);
                    float rs1 = 1.0f / fmaxf(rowsum[r + 8], 1e-8f);
                    v0 *= rs0; v1 *= rs0; v2 *= rs1; v3 *= rs1;
                }
                v0 = geluf(v0 + b0); v1 = geluf(v1 + b1);
                v2 = geluf(v2 + b0); v3 = geluf(v3 + b1);
                if (EP == 3) {
                    float2 r0 = *reinterpret_cast<const float2*>(&resid[i0]);
                    float2 r1 = *reinterpret_cast<const float2*>(&resid[i1]);
                    v0 += r0.x; v1 += r0.y; v2 += r1.x; v3 += r1.y;
                }
                if (EP == 2) {
                    float2 o0 = {v0, v1}, o1 = {v2, v3};
                    *reinterpret_cast<float2*>(&Cf[i0]) = o0;
                    *reinterpret_cast<float2*>(&Cf[i1]) = o1;
                } else {
                    write_split(Ch, Cl, i0, v0, v1);
                    write_split(Ch, Cl, i1, v2, v3);
                }
            }
        }
    }
}

// ---------------- per-row top-K (threshold quick-reject, float4) ------------
__global__ void k_topk2()
{
    __shared__ ull cand[256 * KK];
    __shared__ ull red[256];

    const int row = blockIdx.x;
    const int tid = threadIdx.x;
    const float4* src = reinterpret_cast<const float4*>(&g_Ab[(size_t)row * Nn]);

    ull loc[KK];
    float locv[KK];
    #pragma unroll
    for (int t = 0; t < KK; t++) { loc[t] = 0ULL; locv[t] = -1e30f; }
    float vth = -1e30f;

    for (int q = tid; q < Nn / 4; q += 256) {
        float4 v = __ldcs(src + q);   // streaming: once-touched
        float vv[4] = {v.x, v.y, v.z, v.w};
        #pragma unroll
        for (int e = 0; e < 4; e++) {
            float f = vv[e];
            if (f > vth) {
                int j = q * 4 + e;
                unsigned u = __float_as_uint(f);
                u ^= (u >> 31) ? 0xFFFFFFFFu : 0x80000000u;
                ull key = ((ull)u << 32) | (ull)(0xFFFFFFFFu - (unsigned)j);
                loc[KK - 1] = key; locv[KK - 1] = f;
                #pragma unroll
                for (int t = KK - 1; t > 0; t--) {
                    if (loc[t] > loc[t - 1]) {
                        ull tk = loc[t]; loc[t] = loc[t - 1]; loc[t - 1] = tk;
                        float tv = locv[t]; locv[t] = locv[t - 1]; locv[t - 1] = tv;
                    }
                }
                vth = locv[KK - 1];
            }
        }
    }
    #pragma unroll
    for (int t = 0; t < KK; t++) cand[tid * KK + t] = loc[t];
    __syncthreads();

    for (int t = 0; t < KK; t++) {
        ull m = 0ULL;
        for (int p = tid; p < 256 * KK; p += 256)
            if (cand[p] > m) m = cand[p];
        red[tid] = m;
        __syncthreads();
        for (int s = 128; s > 0; s >>= 1) {
            if (tid < s && red[tid + s] > red[tid]) red[tid] = red[tid + s];
            __syncthreads();
        }
        ull best = red[0];
        if (tid == 0)
            g_top[row * KK + t] = (int)(0xFFFFFFFFu - (unsigned)(best & 0xFFFFFFFFULL));
        for (int p = tid; p < 256 * KK; p += 256)
            if (cand[p] == best) cand[p] = 0ULL;
        __syncthreads();
    }
}

// ---------------- head tail ---------------------------------------------------
__global__ void k_head_tail(const float* __restrict__ wh, const float* __restrict__ bh,
                            float* __restrict__ out, int computeG,
                            const float* __restrict__ gam)
{
    __shared__ float swh[4 * H2s];
    for (int i = threadIdx.x; i < 4 * H2s; i += blockDim.x) {
        int c = i >> 8, d = i & 255;
        swh[i] = wh[d * 4 + c];
    }
    __syncthreads();

    const int warp = threadIdx.x >> 5;
    const int lane = threadIdx.x & 31;
    const int row = blockIdx.x * 8 + warp;

    float a0 = 0.f, a1 = 0.f, a2 = 0.f, a3 = 0.f;
    for (int d = lane; d < H2s; d += 32) {
        float v = g_L2[(size_t)row * H2s + d];
        a0 += v * swh[0 * H2s + d];
        a1 += v * swh[1 * H2s + d];
        a2 += v * swh[2 * H2s + d];
        a3 += v * swh[3 * H2s + d];
    }
    #pragma unroll
    for (int off = 16; off > 0; off >>= 1) {
        a0 += __shfl_xor_sync(0xffffffffu, a0, off);
        a1 += __shfl_xor_sync(0xffffffffu, a1, off);
        a2 += __shfl_xor_sync(0xffffffffu, a2, off);
        a3 += __shfl_xor_sync(0xffffffffu, a3, off);
    }
    if (lane == 0) {
        float r0 = a0 + bh[0], r1 = a1 + bh[1], r2 = a2 + bh[2], r3 = a3 + bh[3];
        float m  = r0;
        float vv = softplusf(r1) + 1e-6f;
        float aa = softplusf(r2) + 1.0f + 1e-6f;
        float bb = softplusf(r3) + 1e-6f;
        out[row]          = m;
        out[Nn + row]     = vv;
        out[2 * Nn + row] = aa;
        out[3 * Nn + row] = bb;
        if (computeG) {
            float u0 = bb / fmaxf(aa - 1.0f, 1e-8f);
            g_G[row] = 1.0f - (*gam) * sigmoidf(u0);
        }
    }
}

// ---------------- mask construction ------------------------------------------
__global__ void k_zero_mask()
{
    size_t idx = (size_t)blockIdx.x * blockDim.x + threadIdx.x;
    size_t total = (size_t)Nn * 256;
    size_t stride = (size_t)gridDim.x * blockDim.x;
    for (size_t p = idx; p < total; p += stride) g_mask[p] = 0u;
}

__global__ void k_set_mask()
{
    int e = blockIdx.x * blockDim.x + threadIdx.x;
    if (e >= Nn * KK) return;
    int i = e / KK;
    int j = g_top[e];
    if (j == i) return;
    atomicOr(&g_mask[i * 256 + (j >> 5)], 1u << (j & 31));
    atomicOr(&g_mask[j * 256 + (i >> 5)], 1u << (i & 31));
}

// ---------------- sparse per-row aggregation (writes Agg split) -------------
#define EB 2048
__global__ void k_edges(const float* __restrict__ X)
{
    __shared__ unsigned int mwords[256];
    __shared__ int sc[256];
    __shared__ int lst[EB];
    __shared__ float cf[EB];
    __shared__ float abv[EB];
    __shared__ float s_rowsum;

    const int row = blockIdx.x;
    const int tid = threadIdx.x;

    unsigned int w0 = g_mask[row * 256 + tid];
    mwords[tid] = w0;
    int myp = __popc(w0);
    sc[tid] = myp;
    __syncthreads();
    for (int off = 1; off < 256; off <<= 1) {
        int v = (tid >= off) ? sc[tid - off] : 0;
        __syncthreads();
        sc[tid] += v;
        __syncthreads();
    }
    const int myoff = sc[tid] - myp;
    const int E = sc[255];
    if (tid == 0) s_rowsum = 0.0f;
    __syncthreads();

    float racc0 = 0.f, racc1 = 0.f, racc2 = 0.f;

    for (int start = 0; start < E; start += EB) {
        int end = (E < start + EB) ? E : (start + EB);
        int cnt = end - start;
        {
            unsigned int w = mwords[tid];
            int pos = myoff;
            while (w) {
                int b = __ffs(w) - 1;
                w &= w - 1;
                if (pos >= start && pos < end) lst[pos - start] = tid * 32 + b;
                pos++;
            }
        }
        __syncthreads();
        for (int e = tid; e < cnt; e += 256) {
            int j = lst[e];
            float ab = g_Ab[(size_t)row * Nn + j];
            abv[e] = ab;
            cf[e] = ab * g_G[j];
        }
        __syncthreads();
        if (tid == 0) {
            float s = s_rowsum;
            for (int e = 0; e < cnt; e++) s += abv[e];
            s_rowsum = s;
        }
        for (int e = 0; e < cnt; e++) {
            float c = cf[e];
            const float* xr = &X[(size_t)lst[e] * Dd];
            racc0 += c * xr[tid];
            racc1 += c * xr[tid + 256];
            racc2 += c * xr[tid + 512];
        }
        __syncthreads();
    }

    const size_t b = (size_t)row * Dd;
    float vs[3] = {racc0, racc1, racc2};
    #pragma unroll
    for (int s = 0; s < 3; s++) {
        bf16 h = __float2bfloat16_rn(vs[s]);
        g_Aggh[b + tid + s * 256] = h;
        g_Aggl[b + tid + s * 256] = __float2bfloat16_rn(vs[s] - __bfloat162float(h));
    }
    if (tid == 0) g_rowsum[row] = s_rowsum;
}

// ---------------- launch ----------------------------------------------------
extern "C" void kernel_launch(void* const* d_in, const int* in_sizes, int n_in,
                              void* d_out, int out_size)
{
    const float* X     = (const float*)d_in[0];
    const float* A     = (const float*)d_in[1];
    const float* W_gm  = (const float*)d_in[2];
    const float* ra    = (const float*)d_in[3];
    const float* gam   = (const float*)d_in[4];
    const float* ih_w1 = (const float*)d_in[5];
    const float* ih_b1 = (const float*)d_in[6];
    const float* ih_w2 = (const float*)d_in[7];
    const float* ih_b2 = (const float*)d_in[8];
    const float* ih_wh = (const float*)d_in[9];
    const float* ih_bh = (const float*)d_in[10];
    const float* gcn_w = (const float*)d_in[11];
    const float* gcn_b = (const float*)d_in[12];
    const float* fh_w1 = (const float*)d_in[13];
    const float* fh_b1 = (const float*)d_in[14];
    const float* fh_w2 = (const float*)d_in[15];
    const float* fh_b2 = (const float*)d_in[16];
    const float* fh_wh = (const float*)d_in[17];
    const float* fh_bh = (const float*)d_in[18];
    float* out = (float*)d_out;

    static float *pAb = nullptr, *pL2 = nullptr, *pRs = nullptr;
    static bf16 *pXh, *pXl, *pYh, *pYl, *pL1h, *pL1l, *pXph, *pXpl, *pAggh, *pAggl;
    static bf16 *pWgmTh, *pWgmTl, *pW1aTh, *pW1aTl, *pW2aTh, *pW2aTl;
    static bf16 *pGcnTh, *pGcnTl, *pW1bTh, *pW1bTl, *pW2bTh, *pW2bTl;
    if (!pAb) {
        cudaGetSymbolAddress((void**)&pAb, g_Ab);
        cudaGetSymbolAddress((void**)&pL2, g_L2);
        cudaGetSymbolAddress((void**)&pRs, g_rowsum);
        cudaGetSymbolAddress((void**)&pXh, g_Xh);   cudaGetSymbolAddress((void**)&pXl, g_Xl);
        cudaGetSymbolAddress((void**)&pYh, g_Yh);   cudaGetSymbolAddress((void**)&pYl, g_Yl);
        cudaGetSymbolAddress((void**)&pL1h, g_L1h); cudaGetSymbolAddress((void**)&pL1l, g_L1l);
        cudaGetSymbolAddress((void**)&pXph, g_Xph); cudaGetSymbolAddress((void**)&pXpl, g_Xpl);
        cudaGetSymbolAddress((void**)&pAggh, g_Aggh); cudaGetSymbolAddress((void**)&pAggl, g_Aggl);
        cudaGetSymbolAddress((void**)&pWgmTh, g_WgmTh); cudaGetSymbolAddress((void**)&pWgmTl, g_WgmTl);
        cudaGetSymbolAddress((void**)&pW1aTh, g_W1aTh); cudaGetSymbolAddress((void**)&pW1aTl, g_W1aTl);
        cudaGetSymbolAddress((void**)&pW2aTh, g_W2aTh); cudaGetSymbolAddress((void**)&pW2aTl, g_W2aTl);
        cudaGetSymbolAddress((void**)&pGcnTh, g_GcnTh); cudaGetSymbolAddress((void**)&pGcnTl, g_GcnTl);
        cudaGetSymbolAddress((void**)&pW1bTh, g_W1bTh); cudaGetSymbolAddress((void**)&pW1bTl, g_W1bTl);
        cudaGetSymbolAddress((void**)&pW2bTh, g_W2bTh); cudaGetSymbolAddress((void**)&pW2bTl, g_W2bTl);
        cudaFuncSetAttribute(k_hmma<0>, cudaFuncAttributeMaxDynamicSharedMemorySize, S_SMEM_BYTES);
        cudaFuncSetAttribute(k_hmma<1>, cudaFuncAttributeMaxDynamicSharedMemorySize, S_SMEM_BYTES);
        cudaFuncSetAttribute(k_hmma<2>, cudaFuncAttributeMaxDynamicSharedMemorySize, S_SMEM_BYTES);
        cudaFuncSetAttribute(k_hmma<3>, cudaFuncAttributeMaxDynamicSharedMemorySize, S_SMEM_BYTES);
        cudaFuncSetAttribute(k_hmma<4>, cudaFuncAttributeMaxDynamicSharedMemorySize, S_SMEM_BYTES);
    }

    dim3 blk(256);
    dim3 blkG(GT);
    dim3 tsb(32, 8);

    // launch order arranged so ncu (-s 5 -c 1) profiles k_hmma<0> (launch #5)
    // 0. X split
    k_split<<<2048, blk>>>(X, pXh, pXl, (size_t)Nn * Dd);
    // 1-3. weight tsplits needed before Y / head1
    k_tsplit<<<dim3(Dd / 32, Dd / 32), tsb>>>(W_gm, pWgmTh, pWgmTl, Dd, Dd);
    k_tsplit<<<dim3(H1s / 32, Dd / 32), tsb>>>(ih_w1, pW1aTh, pW1aTl, Dd, H1s);
    k_tsplit<<<dim3(H2s / 32, H1s / 32), tsb>>>(ih_w2, pW2aTh, pW2aTl, H1s, H2s);
    // 4. Y = X @ W_gm  -> split (EP4)
    k_hmma<4><<<dim3(Dd / 128, Nn / 128), blkG, S_SMEM_BYTES>>>(
        pXh, pXl, pWgmTh, pWgmTl, nullptr, pYh, pYl, Dd, Dd,
        nullptr, nullptr, nullptr, nullptr, nullptr);
    // 5. Ab = al*A + (1-al)*relu(Y @ X^T)  (EP0)   <-- profiled launch
    k_hmma<0><<<dim3(Nn / 128, Nn / 128), blkG, S_SMEM_BYTES>>>(
        pYh, pYl, pXh, pXl, pAb, nullptr, nullptr, Nn, Dd,
        nullptr, nullptr, nullptr, A, ra);

    // 6+. per-row top-5 + union mask
    k_topk2<<<Nn, blk>>>();
    k_zero_mask<<<2048, blk>>>();
    k_set_mask<<<(Nn * KK + 255) / 256, blk>>>();

    // remaining weight tsplits
    k_tsplit<<<dim3(Dd / 32, Dd / 32), tsb>>>(gcn_w, pGcnTh, pGcnTl, Dd, Dd);
    k_tsplit<<<dim3(H1s / 32, Dd / 32), tsb>>>(fh_w1, pW1bTh, pW1bTl, Dd, H1s);
    k_tsplit<<<dim3(H2s / 32, H1s / 32), tsb>>>(fh_w2, pW2bTh, pW2bTl, H1s, H2s);

    // NIG head 1: L1 (EP1), L2 (EP2), head tail (computes G)
    k_hmma<1><<<dim3(H1s / 128, Nn / 128), blkG, S_SMEM_BYTES>>>(
        pXh, pXl, pW1aTh, pW1aTl, nullptr, pL1h, pL1l, H1s, Dd,
        ih_b1, nullptr, nullptr, nullptr, nullptr);
    k_hmma<2><<<dim3(H2s / 128, Nn / 128), blkG, S_SMEM_BYTES>>>(
        pL1h, pL1l, pW2aTh, pW2aTl, pL2, nullptr, nullptr, H2s, H1s,
        ih_b2, nullptr, nullptr, nullptr, nullptr);
    k_head_tail<<<Nn / 8, blk>>>(ih_wh, ih_bh, out, 1, gam);

    // sparse aggregation -> Agg split + rowsum
    k_edges<<<Nn, blk>>>(X);

    // Xp = X + gelu((Agg/rowsum) @ gcn_w + gcn_b)  (EP3 -> split)
    k_hmma<3><<<dim3(Dd / 128, Nn / 128), blkG, S_SMEM_BYTES>>>(
        pAggh, pAggl, pGcnTh, pGcnTl, nullptr, pXph, pXpl, Dd, Dd,
        gcn_b, pRs, X, nullptr, nullptr);

    // NIG head 2
    k_hmma<1><<<dim3(H1s / 128, Nn / 128), blkG, S_SMEM_BYTES>>>(
        pXph, pXpl, pW1bTh, pW1bTl, nullptr, pL1h, pL1l, H1s, Dd,
        fh_b1, nullptr, nullptr, nullptr, nullptr);
    k_hmma<2><<<dim3(H2s / 128, Nn / 128), blkG, S_SMEM_BYTES>>>(
        pL1h, pL1l, pW2bTh, pW2bTl, pL2, nullptr, nullptr, H2s, H1s,
        fh_b2, nullptr, nullptr, nullptr, nullptr);
    k_head_tail<<<Nn / 8, blk>>>(fh_wh, fh_bh, out + 4 * Nn, 0, nullptr);
}

// round 15
// speedup vs baseline: 1.0801x; 1.0801x over previous
#include <cuda_runtime.h>
#include <cuda_bf16.h>
#include <math.h>
#include <stdint.h>

#define Nn 8192
#define Dd 768
#define H1s 512
#define H2s 256
#define KK 5

typedef unsigned long long ull;
typedef __nv_bfloat16 bf16;
typedef __nv_bfloat162 bf162;

// ---------------- scratch (device globals; no allocation allowed) ----------
__device__ float g_Ab[67108864];            // blended score matrix (N x N)
__device__ float g_L2[Nn * H2s];            // fp32 (head_tail input)
__device__ float g_G[Nn];
__device__ int   g_top[Nn * KK];
__device__ float g_rowsum[Nn];
__device__ unsigned int g_mask[Nn * 256];

__device__ bf16 g_Xh[Nn * Dd],  g_Xl[Nn * Dd];
__device__ bf16 g_Yh[Nn * Dd],  g_Yl[Nn * Dd];
__device__ bf16 g_L1h[Nn * H1s], g_L1l[Nn * H1s];
__device__ bf16 g_Xph[Nn * Dd], g_Xpl[Nn * Dd];
__device__ bf16 g_Aggh[Nn * Dd], g_Aggl[Nn * Dd];
__device__ bf16 g_WgmTh[Dd * Dd], g_WgmTl[Dd * Dd];
__device__ bf16 g_W1aTh[H1s * Dd], g_W1aTl[H1s * Dd];
__device__ bf16 g_W2aTh[H2s * H1s], g_W2aTl[H2s * H1s];
__device__ bf16 g_GcnTh[Dd * Dd], g_GcnTl[Dd * Dd];
__device__ bf16 g_W1bTh[H1s * Dd], g_W1bTl[H1s * Dd];
__device__ bf16 g_W2bTh[H2s * H1s], g_W2bTl[H2s * H1s];

// ---------------- math helpers ---------------------------------------------
__device__ __forceinline__ float geluf(float x) {
    return 0.5f * x * (1.0f + erff(x * 0.70710678118654752f));
}
__device__ __forceinline__ float softplusf(float x) {
    return fmaxf(x, 0.0f) + log1pf(expf(-fabsf(x)));
}
__device__ __forceinline__ float sigmoidf(float x) {
    return 1.0f / (1.0f + expf(-x));
}

// ---------------- HMMA m16n8k16 bf16 wrapper ---------------------------------
__device__ __forceinline__ void mma16816(float* d, const uint32_t* a, const uint32_t* b) {
    asm volatile(
        "mma.sync.aligned.m16n8k16.row.col.f32.bf16.bf16.f32 "
        "{%0,%1,%2,%3}, {%4,%5,%6,%7}, {%8,%9}, {%0,%1,%2,%3};"
        : "+f"(d[0]), "+f"(d[1]), "+f"(d[2]), "+f"(d[3])
        : "r"(a[0]), "r"(a[1]), "r"(a[2]), "r"(a[3]), "r"(b[0]), "r"(b[1]));
}
__device__ __forceinline__ uint32_t smem_to_u32(const void* p) {
    uint32_t a;
    asm("{ .reg .u64 t; cvta.to.shared.u64 t, %1; cvt.u32.u64 %0, t; }"
        : "=r"(a) : "l"(p));
    return a;
}
__device__ __forceinline__ void cp_async16(uint32_t dst, const void* src) {
    asm volatile("cp.async.cg.shared.global [%0], [%1], 16;"
                 :: "r"(dst), "l"(src) : "memory");
}
#define CP_COMMIT() asm volatile("cp.async.commit_group;" ::: "memory")
#define CP_WAIT(n)  asm volatile("cp.async.wait_group %0;" :: "n"(n) : "memory")

__device__ __forceinline__ void write_split(bf16* Ch, bf16* Cl, size_t idx,
                                            float v0, float v1) {
    bf16 h0 = __float2bfloat16_rn(v0);
    bf16 h1 = __float2bfloat16_rn(v1);
    bf162 hh; hh.x = h0; hh.y = h1;
    *reinterpret_cast<bf162*>(Ch + idx) = hh;
    bf162 ll;
    ll.x = __float2bfloat16_rn(v0 - __bfloat162float(h0));
    ll.y = __float2bfloat16_rn(v1 - __bfloat162float(h1));
    *reinterpret_cast<bf162*>(Cl + idx) = ll;
}

// ---------------- bf16 split of a fp32 matrix --------------------------------
__global__ void k_split(const float* __restrict__ src,
                        bf16* __restrict__ hi, bf16* __restrict__ lo, size_t total)
{
    size_t idx = (size_t)blockIdx.x * blockDim.x + threadIdx.x;
    size_t stride = (size_t)gridDim.x * blockDim.x;
    for (size_t p = idx; p < total; p += stride) {
        float v = src[p];
        bf16 h = __float2bfloat16_rn(v);
        hi[p] = h;
        lo[p] = __float2bfloat16_rn(v - __bfloat162float(h));
    }
}

// ---------------- transpose + bf16 split of weight: wT[n][k] = w[k][n] ------
__global__ void k_tsplit(const float* __restrict__ w,
                         bf16* __restrict__ th, bf16* __restrict__ tl,
                         int K, int N)
{
    __shared__ float t[32][33];
    const int bx = blockIdx.x * 32;   // along N
    const int by = blockIdx.y * 32;   // along K
    #pragma unroll
    for (int dy = 0; dy < 32; dy += 8)
        t[threadIdx.y + dy][threadIdx.x] =
            w[(size_t)(by + threadIdx.y + dy) * N + bx + threadIdx.x];
    __syncthreads();
    #pragma unroll
    for (int dy = 0; dy < 32; dy += 8) {
        float v = t[threadIdx.x][threadIdx.y + dy];
        size_t o = (size_t)(bx + threadIdx.y + dy) * K + by + threadIdx.x;
        bf16 h = __float2bfloat16_rn(v);
        th[o] = h;
        tl[o] = __float2bfloat16_rn(v - __bfloat162float(h));
    }
}

// ---------------- unified HMMA NT GEMM (bf16 3-term split, fp32 accum) ------
// 128x128 tile/CTA, 16 warps of 32x32, K chunks of 64, 3-stage cp.async
// pipeline with ONE sync per chunk (R13 structure, verified 1675us).
#define SP 72
#define TILE_E (128 * SP)
#define BUF_E (4 * TILE_E)
#define NSTAGE 3
#define S_SMEM_BYTES (NSTAGE * BUF_E * 2)
#define GT 512
template <int EP>
__global__ void __launch_bounds__(GT, 1) k_hmma(
    const bf16* __restrict__ Ah, const bf16* __restrict__ Al,
    const bf16* __restrict__ Bh, const bf16* __restrict__ Bl,
    float* __restrict__ Cf, bf16* __restrict__ Ch, bf16* __restrict__ Cl,
    int Nc, int Kc,
    const float* __restrict__ bias,
    const float* __restrict__ rowsum,
    const float* __restrict__ resid,
    const float* __restrict__ Aecfp,
    const float* __restrict__ ra)
{
    extern __shared__ bf16 sm[];
    const int tid = threadIdx.x;
    const int wid = tid >> 5;
    const int lane = tid & 31;
    const int g = lane >> 2;
    const int t = lane & 3;
    const int bm = blockIdx.y * 128;
    const int bn = blockIdx.x * 128;
    const int m0 = (wid & 3) * 32;     // warp M block
    const int n0 = (wid >> 2) * 32;    // warp N block

    const uint32_t smem_u32 = smem_to_u32(sm);

    float d[2][4][4];
    #pragma unroll
    for (int i = 0; i < 2; i++)
        #pragma unroll
        for (int j = 0; j < 4; j++)
            #pragma unroll
            for (int e = 0; e < 4; e++) d[i][j][e] = 0.0f;

    const int lrow = tid >> 2;         // 0..127
    const int lq   = tid & 3;          // quarter of 128B row (32B each)

    auto issue_load = [&](int buf, int kc) {
        const size_t gAoff = (size_t)(bm + lrow) * Kc + kc * 64 + lq * 16;
        const size_t gBoff = (size_t)(bn + lrow) * Kc + kc * 64 + lq * 16;
        const uint32_t soff = (buf * BUF_E + lrow * SP + lq * 16) * 2;   // bytes
        #pragma unroll
        for (int q = 0; q < 2; q++) {
            cp_async16(smem_u32 + soff + q * 16,              Ah + gAoff + q * 8);
            cp_async16(smem_u32 + soff + TILE_E * 2 + q * 16, Al + gAoff + q * 8);
            cp_async16(smem_u32 + soff + TILE_E * 4 + q * 16, Bh + gBoff + q * 8);
            cp_async16(smem_u32 + soff + TILE_E * 6 + q * 16, Bl + gBoff + q * 8);
        }
        CP_COMMIT();
    };

    const int NCHUNK = Kc / 64;
    issue_load(0, 0);
    issue_load(1, 1);

    for (int kc = 0; kc < NCHUNK; kc++) {
        if (kc + 1 < NCHUNK) { CP_WAIT(1); }
        else                 { CP_WAIT(0); }
        __syncthreads();

        const int buf = kc % NSTAGE;
        const bf16* sAh = sm + buf * BUF_E;
        const bf16* sAl = sAh + TILE_E;
        const bf16* sBh = sAl + TILE_E;
        const bf16* sBl = sBh + TILE_E;

        #pragma unroll
        for (int ks = 0; ks < 4; ks++) {
            const int k0 = ks * 16;
            uint32_t ah[2][4], al2[2][4], bh[4][2], bl[4][2];
            #pragma unroll
            for (int ma = 0; ma < 2; ma++) {
                int r = m0 + ma * 16 + g;
                int c = k0 + t * 2;
                ah[ma][0] = *(const uint32_t*)&sAh[r * SP + c];
                ah[ma][1] = *(const uint32_t*)&sAh[(r + 8) * SP + c];
                ah[ma][2] = *(const uint32_t*)&sAh[r * SP + c + 8];
                ah[ma][3] = *(const uint32_t*)&sAh[(r + 8) * SP + c + 8];
                al2[ma][0] = *(const uint32_t*)&sAl[r * SP + c];
                al2[ma][1] = *(const uint32_t*)&sAl[(r + 8) * SP + c];
                al2[ma][2] = *(const uint32_t*)&sAl[r * SP + c + 8];
                al2[ma][3] = *(const uint32_t*)&sAl[(r + 8) * SP + c + 8];
            }
            #pragma unroll
            for (int na = 0; na < 4; na++) {
                int n = n0 + na * 8 + g;
                bh[na][0] = *(const uint32_t*)&sBh[n * SP + k0 + t * 2];
                bh[na][1] = *(const uint32_t*)&sBh[n * SP + k0 + 8 + t * 2];
                bl[na][0] = *(const uint32_t*)&sBl[n * SP + k0 + t * 2];
                bl[na][1] = *(const uint32_t*)&sBl[n * SP + k0 + 8 + t * 2];
            }
            #pragma unroll
            for (int ma = 0; ma < 2; ma++)
                #pragma unroll
                for (int na = 0; na < 4; na++)
                    mma16816(d[ma][na], ah[ma], bh[na]);
            #pragma unroll
            for (int ma = 0; ma < 2; ma++)
                #pragma unroll
                for (int na = 0; na < 4; na++)
                    mma16816(d[ma][na], ah[ma], bl[na]);
            #pragma unroll
            for (int ma = 0; ma < 2; ma++)
                #pragma unroll
                for (int na = 0; na < 4; na++)
                    mma16816(d[ma][na], al2[ma], bh[na]);
        }

        if (kc + 2 < NCHUNK) issue_load((kc + 2) % NSTAGE, kc + 2);
    }

    // ---- epilogue
    float alv = 0.f, om = 0.f;
    if (EP == 0) { alv = sigmoidf(*ra); om = __fsub_rn(1.0f, alv); }

    #pragma unroll
    for (int ma = 0; ma < 2; ma++) {
        #pragma unroll
        for (int na = 0; na < 4; na++) {
            const int r = bm + m0 + ma * 16 + g;
            const int c = bn + n0 + na * 8 + t * 2;
            const size_t i0 = (size_t)r * Nc + c;
            const size_t i1 = (size_t)(r + 8) * Nc + c;
            float v0 = d[ma][na][0], v1 = d[ma][na][1];
            float v2 = d[ma][na][2], v3 = d[ma][na][3];

            if (EP == 0) {
                float2 a0 = *reinterpret_cast<const float2*>(&Aecfp[i0]);
                float2 a1 = *reinterpret_cast<const float2*>(&Aecfp[i1]);
                float2 o0, o1;
                o0.x = __fadd_rn(__fmul_rn(alv, a0.x), __fmul_rn(om, fmaxf(v0, 0.0f)));
                o0.y = __fadd_rn(__fmul_rn(alv, a0.y), __fmul_rn(om, fmaxf(v1, 0.0f)));
                o1.x = __fadd_rn(__fmul_rn(alv, a1.x), __fmul_rn(om, fmaxf(v2, 0.0f)));
                o1.y = __fadd_rn(__fmul_rn(alv, a1.y), __fmul_rn(om, fmaxf(v3, 0.0f)));
                *reinterpret_cast<float2*>(&Cf[i0]) = o0;
                *reinterpret_cast<float2*>(&Cf[i1]) = o1;
            } else if (EP == 4) {
                write_split(Ch, Cl, i0, v0, v1);
                write_split(Ch, Cl, i1, v2, v3);
            } else {
                const float b0 = bias[c], b1 = bias[c + 1];
                if (EP == 3) {
                    float rs0 = 1.0f / fmaxf(rowsum[r], 1e-8f);
                    float rs1 = 1.0f / fmaxf(rowsum[r + 8], 1e-8f);
                    v0 *= rs0; v1 *= rs0; v2 *= rs1; v3 *= rs1;
                }
                v0 = geluf(v0 + b0); v1 = geluf(v1 + b1);
                v2 = geluf(v2 + b0); v3 = geluf(v3 + b1);
                if (EP == 3) {
                    float2 r0 = *reinterpret_cast<const float2*>(&resid[i0]);
                    float2 r1 = *reinterpret_cast<const float2*>(&resid[i1]);
                    v0 += r0.x; v1 += r0.y; v2 += r1.x; v3 += r1.y;
                }
                if (EP == 2) {
                    float2 o0 = {v0, v1}, o1 = {v2, v3};
                    *reinterpret_cast<float2*>(&Cf[i0]) = o0;
                    *reinterpret_cast<float2*>(&Cf[i1]) = o1;
                } else {
                    write_split(Ch, Cl, i0, v0, v1);
                    write_split(Ch, Cl, i1, v2, v3);
                }
            }
        }
    }
}

// ---------------- per-row top-K (threshold quick-reject, float4) ------------
__global__ void k_topk2()
{
    __shared__ ull cand[256 * KK];
    __shared__ ull red[256];

    const int row = blockIdx.x;
    const int tid = threadIdx.x;
    const float4* src = reinterpret_cast<const float4*>(&g_Ab[(size_t)row * Nn]);

    ull loc[KK];
    float locv[KK];
    #pragma unroll
    for (int t = 0; t < KK; t++) { loc[t] = 0ULL; locv[t] = -1e30f; }
    float vth = -1e30f;

    for (int q = tid; q < Nn / 4; q += 256) {
        float4 v = src[q];
        float vv[4] = {v.x, v.y, v.z, v.w};
        #pragma unroll
        for (int e = 0; e < 4; e++) {
            float f = vv[e];
            if (f > vth) {
                int j = q * 4 + e;
                unsigned u = __float_as_uint(f);
                u ^= (u >> 31) ? 0xFFFFFFFFu : 0x80000000u;
                ull key = ((ull)u << 32) | (ull)(0xFFFFFFFFu - (unsigned)j);
                loc[KK - 1] = key; locv[KK - 1] = f;
                #pragma unroll
                for (int t = KK - 1; t > 0; t--) {
                    if (loc[t] > loc[t - 1]) {
                        ull tk = loc[t]; loc[t] = loc[t - 1]; loc[t - 1] = tk;
                        float tv = locv[t]; locv[t] = locv[t - 1]; locv[t - 1] = tv;
                    }
                }
                vth = locv[KK - 1];
            }
        }
    }
    #pragma unroll
    for (int t = 0; t < KK; t++) cand[tid * KK + t] = loc[t];
    __syncthreads();

    for (int t = 0; t < KK; t++) {
        ull m = 0ULL;
        for (int p = tid; p < 256 * KK; p += 256)
            if (cand[p] > m) m = cand[p];
        red[tid] = m;
        __syncthreads();
        for (int s = 128; s > 0; s >>= 1) {
            if (tid < s && red[tid + s] > red[tid]) red[tid] = red[tid + s];
            __syncthreads();
        }
        ull best = red[0];
        if (tid == 0)
            g_top[row * KK + t] = (int)(0xFFFFFFFFu - (unsigned)(best & 0xFFFFFFFFULL));
        for (int p = tid; p < 256 * KK; p += 256)
            if (cand[p] == best) cand[p] = 0ULL;
        __syncthreads();
    }
}

// ---------------- head tail ---------------------------------------------------
__global__ void k_head_tail(const float* __restrict__ wh, const float* __restrict__ bh,
                            float* __restrict__ out, int computeG,
                            const float* __restrict__ gam)
{
    __shared__ float swh[4 * H2s];
    for (int i = threadIdx.x; i < 4 * H2s; i += blockDim.x) {
        int c = i >> 8, d = i & 255;
        swh[i] = wh[d * 4 + c];
    }
    __syncthreads();

    const int warp = threadIdx.x >> 5;
    const int lane = threadIdx.x & 31;
    const int row = blockIdx.x * 8 + warp;

    float a0 = 0.f, a1 = 0.f, a2 = 0.f, a3 = 0.f;
    for (int d = lane; d < H2s; d += 32) {
        float v = g_L2[(size_t)row * H2s + d];
        a0 += v * swh[0 * H2s + d];
        a1 += v * swh[1 * H2s + d];
        a2 += v * swh[2 * H2s + d];
        a3 += v * swh[3 * H2s + d];
    }
    #pragma unroll
    for (int off = 16; off > 0; off >>= 1) {
        a0 += __shfl_xor_sync(0xffffffffu, a0, off);
        a1 += __shfl_xor_sync(0xffffffffu, a1, off);
        a2 += __shfl_xor_sync(0xffffffffu, a2, off);
        a3 += __shfl_xor_sync(0xffffffffu, a3, off);
    }
    if (lane == 0) {
        float r0 = a0 + bh[0], r1 = a1 + bh[1], r2 = a2 + bh[2], r3 = a3 + bh[3];
        float m  = r0;
        float vv = softplusf(r1) + 1e-6f;
        float aa = softplusf(r2) + 1.0f + 1e-6f;
        float bb = softplusf(r3) + 1e-6f;
        out[row]          = m;
        out[Nn + row]     = vv;
        out[2 * Nn + row] = aa;
        out[3 * Nn + row] = bb;
        if (computeG) {
            float u0 = bb / fmaxf(aa - 1.0f, 1e-8f);
            g_G[row] = 1.0f - (*gam) * sigmoidf(u0);
        }
    }
}

// ---------------- mask construction ------------------------------------------
__global__ void k_zero_mask()
{
    size_t idx = (size_t)blockIdx.x * blockDim.x + threadIdx.x;
    size_t total = (size_t)Nn * 256;
    size_t stride = (size_t)gridDim.x * blockDim.x;
    for (size_t p = idx; p < total; p += stride) g_mask[p] = 0u;
}

__global__ void k_set_mask()
{
    int e = blockIdx.x * blockDim.x + threadIdx.x;
    if (e >= Nn * KK) return;
    int i = e / KK;
    int j = g_top[e];
    if (j == i) return;
    atomicOr(&g_mask[i * 256 + (j >> 5)], 1u << (j & 31));
    atomicOr(&g_mask[j * 256 + (i >> 5)], 1u << (i & 31));
}

// ---------------- sparse per-row aggregation (writes Agg split) -------------
#define EB 2048
__global__ void k_edges(const float* __restrict__ X)
{
    __shared__ unsigned int mwords[256];
    __shared__ int sc[256];
    __shared__ int lst[EB];
    __shared__ float cf[EB];
    __shared__ float abv[EB];
    __shared__ float s_rowsum;

    const int row = blockIdx.x;
    const int tid = threadIdx.x;

    unsigned int w0 = g_mask[row * 256 + tid];
    mwords[tid] = w0;
    int myp = __popc(w0);
    sc[tid] = myp;
    __syncthreads();
    for (int off = 1; off < 256; off <<= 1) {
        int v = (tid >= off) ? sc[tid - off] : 0;
        __syncthreads();
        sc[tid] += v;
        __syncthreads();
    }
    const int myoff = sc[tid] - myp;
    const int E = sc[255];
    if (tid == 0) s_rowsum = 0.0f;
    __syncthreads();

    float racc0 = 0.f, racc1 = 0.f, racc2 = 0.f;

    for (int start = 0; start < E; start += EB) {
        int end = (E < start + EB) ? E : (start + EB);
        int cnt = end - start;
        {
            unsigned int w = mwords[tid];
            int pos = myoff;
            while (w) {
                int b = __ffs(w) - 1;
                w &= w - 1;
                if (pos >= start && pos < end) lst[pos - start] = tid * 32 + b;
                pos++;
            }
        }
        __syncthreads();
        for (int e = tid; e < cnt; e += 256) {
            int j = lst[e];
            float ab = g_Ab[(size_t)row * Nn + j];
            abv[e] = ab;
            cf[e] = ab * g_G[j];
        }
        __syncthreads();
        if (tid == 0) {
            float s = s_rowsum;
            for (int e = 0; e < cnt; e++) s += abv[e];
            s_rowsum = s;
        }
        for (int e = 0; e < cnt; e++) {
            float c = cf[e];
            const float* xr = &X[(size_t)lst[e] * Dd];
            racc0 += c * xr[tid];
            racc1 += c * xr[tid + 256];
            racc2 += c * xr[tid + 512];
        }
        __syncthreads();
    }

    const size_t b = (size_t)row * Dd;
    float vs[3] = {racc0, racc1, racc2};
    #pragma unroll
    for (int s = 0; s < 3; s++) {
        bf16 h = __float2bfloat16_rn(vs[s]);
        g_Aggh[b + tid + s * 256] = h;
        g_Aggl[b + tid + s * 256] = __float2bfloat16_rn(vs[s] - __bfloat162float(h));
    }
    if (tid == 0) g_rowsum[row] = s_rowsum;
}

// ---------------- launch ----------------------------------------------------
extern "C" void kernel_launch(void* const* d_in, const int* in_sizes, int n_in,
                              void* d_out, int out_size)
{
    const float* X     = (const float*)d_in[0];
    const float* A     = (const float*)d_in[1];
    const float* W_gm  = (const float*)d_in[2];
    const float* ra    = (const float*)d_in[3];
    const float* gam   = (const float*)d_in[4];
    const float* ih_w1 = (const float*)d_in[5];
    const float* ih_b1 = (const float*)d_in[6];
    const float* ih_w2 = (const float*)d_in[7];
    const float* ih_b2 = (const float*)d_in[8];
    const float* ih_wh = (const float*)d_in[9];
    const float* ih_bh = (const float*)d_in[10];
    const float* gcn_w = (const float*)d_in[11];
    const float* gcn_b = (const float*)d_in[12];
    const float* fh_w1 = (const float*)d_in[13];
    const float* fh_b1 = (const float*)d_in[14];
    const float* fh_w2 = (const float*)d_in[15];
    const float* fh_b2 = (const float*)d_in[16];
    const float* fh_wh = (const float*)d_in[17];
    const float* fh_bh = (const float*)d_in[18];
    float* out = (float*)d_out;

    static float *pAb = nullptr, *pL2 = nullptr, *pRs = nullptr;
    static bf16 *pXh, *pXl, *pYh, *pYl, *pL1h, *pL1l, *pXph, *pXpl, *pAggh, *pAggl;
    static bf16 *pWgmTh, *pWgmTl, *pW1aTh, *pW1aTl, *pW2aTh, *pW2aTl;
    static bf16 *pGcnTh, *pGcnTl, *pW1bTh, *pW1bTl, *pW2bTh, *pW2bTl;
    static cudaStream_t s2 = nullptr;
    static cudaEvent_t evFork = nullptr, evJoin = nullptr;
    if (!pAb) {
        cudaGetSymbolAddress((void**)&pAb, g_Ab);
        cudaGetSymbolAddress((void**)&pL2, g_L2);
        cudaGetSymbolAddress((void**)&pRs, g_rowsum);
        cudaGetSymbolAddress((void**)&pXh, g_Xh);   cudaGetSymbolAddress((void**)&pXl, g_Xl);
        cudaGetSymbolAddress((void**)&pYh, g_Yh);   cudaGetSymbolAddress((void**)&pYl, g_Yl);
        cudaGetSymbolAddress((void**)&pL1h, g_L1h); cudaGetSymbolAddress((void**)&pL1l, g_L1l);
        cudaGetSymbolAddress((void**)&pXph, g_Xph); cudaGetSymbolAddress((void**)&pXpl, g_Xpl);
        cudaGetSymbolAddress((void**)&pAggh, g_Aggh); cudaGetSymbolAddress((void**)&pAggl, g_Aggl);
        cudaGetSymbolAddress((void**)&pWgmTh, g_WgmTh); cudaGetSymbolAddress((void**)&pWgmTl, g_WgmTl);
        cudaGetSymbolAddress((void**)&pW1aTh, g_W1aTh); cudaGetSymbolAddress((void**)&pW1aTl, g_W1aTl);
        cudaGetSymbolAddress((void**)&pW2aTh, g_W2aTh); cudaGetSymbolAddress((void**)&pW2aTl, g_W2aTl);
        cudaGetSymbolAddress((void**)&pGcnTh, g_GcnTh); cudaGetSymbolAddress((void**)&pGcnTl, g_GcnTl);
        cudaGetSymbolAddress((void**)&pW1bTh, g_W1bTh); cudaGetSymbolAddress((void**)&pW1bTl, g_W1bTl);
        cudaGetSymbolAddress((void**)&pW2bTh, g_W2bTh); cudaGetSymbolAddress((void**)&pW2bTl, g_W2bTl);
        cudaFuncSetAttribute(k_hmma<0>, cudaFuncAttributeMaxDynamicSharedMemorySize, S_SMEM_BYTES);
        cudaFuncSetAttribute(k_hmma<1>, cudaFuncAttributeMaxDynamicSharedMemorySize, S_SMEM_BYTES);
        cudaFuncSetAttribute(k_hmma<2>, cudaFuncAttributeMaxDynamicSharedMemorySize, S_SMEM_BYTES);
        cudaFuncSetAttribute(k_hmma<3>, cudaFuncAttributeMaxDynamicSharedMemorySize, S_SMEM_BYTES);
        cudaFuncSetAttribute(k_hmma<4>, cudaFuncAttributeMaxDynamicSharedMemorySize, S_SMEM_BYTES);
        cudaStreamCreateWithFlags(&s2, cudaStreamNonBlocking);
        cudaEventCreateWithFlags(&evFork, cudaEventDisableTiming);
        cudaEventCreateWithFlags(&evJoin, cudaEventDisableTiming);
    }

    dim3 blk(256);
    dim3 blkG(GT);
    dim3 tsb(32, 8);
    cudaStream_t s0 = 0;   // legacy default (captured)

    // ---- main path (s0): X split -> Y -> S -> topk -> mask
    k_split<<<2048, blk, 0, s0>>>(X, pXh, pXl, (size_t)Nn * Dd);
    cudaEventRecord(evFork, s0);

    // ---- side path (s2): head-1 chain + remaining weight tsplits
    cudaStreamWaitEvent(s2, evFork, 0);
    k_tsplit<<<dim3(H1s / 32, Dd / 32), tsb, 0, s2>>>(ih_w1, pW1aTh, pW1aTl, Dd, H1s);
    k_tsplit<<<dim3(H2s / 32, H1s / 32), tsb, 0, s2>>>(ih_w2, pW2aTh, pW2aTl, H1s, H2s);
    k_tsplit<<<dim3(Dd / 32, Dd / 32), tsb, 0, s2>>>(gcn_w, pGcnTh, pGcnTl, Dd, Dd);
    k_tsplit<<<dim3(H1s / 32, Dd / 32), tsb, 0, s2>>>(fh_w1, pW1bTh, pW1bTl, Dd, H1s);
    k_tsplit<<<dim3(H2s / 32, H1s / 32), tsb, 0, s2>>>(fh_w2, pW2bTh, pW2bTl, H1s, H2s);
    k_hmma<1><<<dim3(H1s / 128, Nn / 128), blkG, S_SMEM_BYTES, s2>>>(
        pXh, pXl, pW1aTh, pW1aTl, nullptr, pL1h, pL1l, H1s, Dd,
        ih_b1, nullptr, nullptr, nullptr, nullptr);
    k_hmma<2><<<dim3(H2s / 128, Nn / 128), blkG, S_SMEM_BYTES, s2>>>(
        pL1h, pL1l, pW2aTh, pW2aTl, pL2, nullptr, nullptr, H2s, H1s,
        ih_b2, nullptr, nullptr, nullptr, nullptr);
    k_head_tail<<<Nn / 8, blk, 0, s2>>>(ih_wh, ih_bh, out, 1, gam);
    cudaEventRecord(evJoin, s2);

    // ---- main path continues (s0)
    k_tsplit<<<dim3(Dd / 32, Dd / 32), tsb, 0, s0>>>(W_gm, pWgmTh, pWgmTl, Dd, Dd);
    k_hmma<4><<<dim3(Dd / 128, Nn / 128), blkG, S_SMEM_BYTES, s0>>>(
        pXh, pXl, pWgmTh, pWgmTl, nullptr, pYh, pYl, Dd, Dd,
        nullptr, nullptr, nullptr, nullptr, nullptr);
    k_hmma<0><<<dim3(Nn / 128, Nn / 128), blkG, S_SMEM_BYTES, s0>>>(
        pYh, pYl, pXh, pXl, pAb, nullptr, nullptr, Nn, Dd,
        nullptr, nullptr, nullptr, A, ra);
    k_topk2<<<Nn, blk, 0, s0>>>();
    k_zero_mask<<<2048, blk, 0, s0>>>();
    k_set_mask<<<(Nn * KK + 255) / 256, blk, 0, s0>>>();

    // ---- join: edges needs G (s2) + mask + Ab (s0)
    cudaStreamWaitEvent(s0, evJoin, 0);
    k_edges<<<Nn, blk, 0, s0>>>(X);

    // Xp = X + gelu((Agg/rowsum) @ gcn_w + gcn_b)  (EP3 -> split)
    k_hmma<3><<<dim3(Dd / 128, Nn / 128), blkG, S_SMEM_BYTES, s0>>>(
        pAggh, pAggl, pGcnTh, pGcnTl, nullptr, pXph, pXpl, Dd, Dd,
        gcn_b, pRs, X, nullptr, nullptr);

    // NIG head 2
    k_hmma<1><<<dim3(H1s / 128, Nn / 128), blkG, S_SMEM_BYTES, s0>>>(
        pXph, pXpl, pW1bTh, pW1bTl, nullptr, pL1h, pL1l, H1s, Dd,
        fh_b1, nullptr, nullptr, nullptr, nullptr);
    k_hmma<2><<<dim3(H2s / 128, Nn / 128), blkG, S_SMEM_BYTES, s0>>>(
        pL1h, pL1l, pW2bTh, pW2bTl, pL2, nullptr, nullptr, H2s, H1s,
        fh_b2, nullptr, nullptr, nullptr, nullptr);
    k_head_tail<<<Nn / 8, blk, 0, s0>>>(fh_wh, fh_bh, out + 4 * Nn, 0, nullptr);
}

// round 16
// speedup vs baseline: 1.0808x; 1.0007x over previous
#include <cuda_runtime.h>
#include <cuda_bf16.h>
#include <math.h>
#include <stdint.h>

#define Nn 8192
#define Dd 768
#define H1s 512
#define H2s 256
#define KK 5

typedef unsigned long long ull;
typedef __nv_bfloat16 bf16;
typedef __nv_bfloat162 bf162;

// ---------------- scratch (device globals; no allocation allowed) ----------
__device__ float g_Ab[67108864];            // blended score matrix (N x N)
__device__ float g_L2[Nn * H2s];            // fp32 (head_tail input)
__device__ float g_G[Nn];
__device__ int   g_top[Nn * KK];
__device__ float g_rowsum[Nn];
__device__ unsigned int g_mask[Nn * 256];

__device__ bf16 g_Xh[Nn * Dd],  g_Xl[Nn * Dd];
__device__ bf16 g_Yh[Nn * Dd],  g_Yl[Nn * Dd];
__device__ bf16 g_L1h[Nn * H1s], g_L1l[Nn * H1s];
__device__ bf16 g_Xph[Nn * Dd], g_Xpl[Nn * Dd];
__device__ bf16 g_Aggh[Nn * Dd], g_Aggl[Nn * Dd];
__device__ bf16 g_WgmTh[Dd * Dd], g_WgmTl[Dd * Dd];
__device__ bf16 g_W1aTh[H1s * Dd], g_W1aTl[H1s * Dd];
__device__ bf16 g_W2aTh[H2s * H1s], g_W2aTl[H2s * H1s];
__device__ bf16 g_GcnTh[Dd * Dd], g_GcnTl[Dd * Dd];
__device__ bf16 g_W1bTh[H1s * Dd], g_W1bTl[H1s * Dd];
__device__ bf16 g_W2bTh[H2s * H1s], g_W2bTl[H2s * H1s];

// ---------------- math helpers ---------------------------------------------
__device__ __forceinline__ float geluf(float x) {
    return 0.5f * x * (1.0f + erff(x * 0.70710678118654752f));
}
__device__ __forceinline__ float softplusf(float x) {
    return fmaxf(x, 0.0f) + log1pf(expf(-fabsf(x)));
}
__device__ __forceinline__ float sigmoidf(float x) {
    return 1.0f / (1.0f + expf(-x));
}

// ---------------- HMMA m16n8k16 bf16 wrapper ---------------------------------
__device__ __forceinline__ void mma16816(float* d, const uint32_t* a, const uint32_t* b) {
    asm volatile(
        "mma.sync.aligned.m16n8k16.row.col.f32.bf16.bf16.f32 "
        "{%0,%1,%2,%3}, {%4,%5,%6,%7}, {%8,%9}, {%0,%1,%2,%3};"
        : "+f"(d[0]), "+f"(d[1]), "+f"(d[2]), "+f"(d[3])
        : "r"(a[0]), "r"(a[1]), "r"(a[2]), "r"(a[3]), "r"(b[0]), "r"(b[1]));
}
__device__ __forceinline__ uint32_t smem_to_u32(const void* p) {
    uint32_t a;
    asm("{ .reg .u64 t; cvta.to.shared.u64 t, %1; cvt.u32.u64 %0, t; }"
        : "=r"(a) : "l"(p));
    return a;
}
__device__ __forceinline__ void cp_async16(uint32_t dst, const void* src) {
    asm volatile("cp.async.cg.shared.global [%0], [%1], 16;"
                 :: "r"(dst), "l"(src) : "memory");
}
#define CP_COMMIT() asm volatile("cp.async.commit_group;" ::: "memory")
#define CP_WAIT(n)  asm volatile("cp.async.wait_group %0;" :: "n"(n) : "memory")

__device__ __forceinline__ void write_split(bf16* Ch, bf16* Cl, size_t idx,
                                            float v0, float v1) {
    bf16 h0 = __float2bfloat16_rn(v0);
    bf16 h1 = __float2bfloat16_rn(v1);
    bf162 hh; hh.x = h0; hh.y = h1;
    *reinterpret_cast<bf162*>(Ch + idx) = hh;
    bf162 ll;
    ll.x = __float2bfloat16_rn(v0 - __bfloat162float(h0));
    ll.y = __float2bfloat16_rn(v1 - __bfloat162float(h1));
    *reinterpret_cast<bf162*>(Cl + idx) = ll;
}

// ---------------- bf16 split of a fp32 matrix --------------------------------
__global__ void k_split(const float* __restrict__ src,
                        bf16* __restrict__ hi, bf16* __restrict__ lo, size_t total)
{
    size_t idx = (size_t)blockIdx.x * blockDim.x + threadIdx.x;
    size_t stride = (size_t)gridDim.x * blockDim.x;
    for (size_t p = idx; p < total; p += stride) {
        float v = src[p];
        bf16 h = __float2bfloat16_rn(v);
        hi[p] = h;
        lo[p] = __float2bfloat16_rn(v - __bfloat162float(h));
    }
}

// ---------------- transpose + bf16 split of weight: wT[n][k] = w[k][n] ------
__global__ void k_tsplit(const float* __restrict__ w,
                         bf16* __restrict__ th, bf16* __restrict__ tl,
                         int K, int N)
{
    __shared__ float t[32][33];
    const int bx = blockIdx.x * 32;   // along N
    const int by = blockIdx.y * 32;   // along K
    #pragma unroll
    for (int dy = 0; dy < 32; dy += 8)
        t[threadIdx.y + dy][threadIdx.x] =
            w[(size_t)(by + threadIdx.y + dy) * N + bx + threadIdx.x];
    __syncthreads();
    #pragma unroll
    for (int dy = 0; dy < 32; dy += 8) {
        float v = t[threadIdx.x][threadIdx.y + dy];
        size_t o = (size_t)(bx + threadIdx.y + dy) * K + by + threadIdx.x;
        bf16 h = __float2bfloat16_rn(v);
        th[o] = h;
        tl[o] = __float2bfloat16_rn(v - __bfloat162float(h));
    }
}

// ---------------- unified HMMA NT GEMM (bf16 3-term split, fp32 accum) ------
// 128x128 tile/CTA, 16 warps of 32x32, K chunks of 64, 3-stage cp.async
// pipeline with ONE sync per chunk (verified structure, 1616us).
// byOff: row-tile offset (for split launches of the big S GEMM).
#define SP 72
#define TILE_E (128 * SP)
#define BUF_E (4 * TILE_E)
#define NSTAGE 3
#define S_SMEM_BYTES (NSTAGE * BUF_E * 2)
#define GT 512
template <int EP>
__global__ void __launch_bounds__(GT, 1) k_hmma(
    const bf16* __restrict__ Ah, const bf16* __restrict__ Al,
    const bf16* __restrict__ Bh, const bf16* __restrict__ Bl,
    float* __restrict__ Cf, bf16* __restrict__ Ch, bf16* __restrict__ Cl,
    int Nc, int Kc, int byOff,
    const float* __restrict__ bias,
    const float* __restrict__ rowsum,
    const float* __restrict__ resid,
    const float* __restrict__ Aecfp,
    const float* __restrict__ ra)
{
    extern __shared__ bf16 sm[];
    const int tid = threadIdx.x;
    const int wid = tid >> 5;
    const int lane = tid & 31;
    const int g = lane >> 2;
    const int t = lane & 3;
    const int bm = (blockIdx.y + byOff) * 128;
    const int bn = blockIdx.x * 128;
    const int m0 = (wid & 3) * 32;     // warp M block
    const int n0 = (wid >> 2) * 32;    // warp N block

    const uint32_t smem_u32 = smem_to_u32(sm);

    float d[2][4][4];
    #pragma unroll
    for (int i = 0; i < 2; i++)
        #pragma unroll
        for (int j = 0; j < 4; j++)
            #pragma unroll
            for (int e = 0; e < 4; e++) d[i][j][e] = 0.0f;

    const int lrow = tid >> 2;         // 0..127
    const int lq   = tid & 3;          // quarter of 128B row (32B each)

    auto issue_load = [&](int buf, int kc) {
        const size_t gAoff = (size_t)(bm + lrow) * Kc + kc * 64 + lq * 16;
        const size_t gBoff = (size_t)(bn + lrow) * Kc + kc * 64 + lq * 16;
        const uint32_t soff = (buf * BUF_E + lrow * SP + lq * 16) * 2;   // bytes
        #pragma unroll
        for (int q = 0; q < 2; q++) {
            cp_async16(smem_u32 + soff + q * 16,              Ah + gAoff + q * 8);
            cp_async16(smem_u32 + soff + TILE_E * 2 + q * 16, Al + gAoff + q * 8);
            cp_async16(smem_u32 + soff + TILE_E * 4 + q * 16, Bh + gBoff + q * 8);
            cp_async16(smem_u32 + soff + TILE_E * 6 + q * 16, Bl + gBoff + q * 8);
        }
        CP_COMMIT();
    };

    const int NCHUNK = Kc / 64;
    issue_load(0, 0);
    issue_load(1, 1);

    for (int kc = 0; kc < NCHUNK; kc++) {
        if (kc + 1 < NCHUNK) { CP_WAIT(1); }
        else                 { CP_WAIT(0); }
        __syncthreads();

        const int buf = kc % NSTAGE;
        const bf16* sAh = sm + buf * BUF_E;
        const bf16* sAl = sAh + TILE_E;
        const bf16* sBh = sAl + TILE_E;
        const bf16* sBl = sBh + TILE_E;

        #pragma unroll
        for (int ks = 0; ks < 4; ks++) {
            const int k0 = ks * 16;
            uint32_t ah[2][4], al2[2][4], bh[4][2], bl[4][2];
            #pragma unroll
            for (int ma = 0; ma < 2; ma++) {
                int r = m0 + ma * 16 + g;
                int c = k0 + t * 2;
                ah[ma][0] = *(const uint32_t*)&sAh[r * SP + c];
                ah[ma][1] = *(const uint32_t*)&sAh[(r + 8) * SP + c];
                ah[ma][2] = *(const uint32_t*)&sAh[r * SP + c + 8];
                ah[ma][3] = *(const uint32_t*)&sAh[(r + 8) * SP + c + 8];
                al2[ma][0] = *(const uint32_t*)&sAl[r * SP + c];
                al2[ma][1] = *(const uint32_t*)&sAl[(r + 8) * SP + c];
                al2[ma][2] = *(const uint32_t*)&sAl[r * SP + c + 8];
                al2[ma][3] = *(const uint32_t*)&sAl[(r + 8) * SP + c + 8];
            }
            #pragma unroll
            for (int na = 0; na < 4; na++) {
                int n = n0 + na * 8 + g;
                bh[na][0] = *(const uint32_t*)&sBh[n * SP + k0 + t * 2];
                bh[na][1] = *(const uint32_t*)&sBh[n * SP + k0 + 8 + t * 2];
                bl[na][0] = *(const uint32_t*)&sBl[n * SP + k0 + t * 2];
                bl[na][1] = *(const uint32_t*)&sBl[n * SP + k0 + 8 + t * 2];
            }
            #pragma unroll
            for (int ma = 0; ma < 2; ma++)
                #pragma unroll
                for (int na = 0; na < 4; na++)
                    mma16816(d[ma][na], ah[ma], bh[na]);
            #pragma unroll
            for (int ma = 0; ma < 2; ma++)
                #pragma unroll
                for (int na = 0; na < 4; na++)
                    mma16816(d[ma][na], ah[ma], bl[na]);
            #pragma unroll
            for (int ma = 0; ma < 2; ma++)
                #pragma unroll
                for (int na = 0; na < 4; na++)
                    mma16816(d[ma][na], al2[ma], bh[na]);
        }

        if (kc + 2 < NCHUNK) issue_load((kc + 2) % NSTAGE, kc + 2);
    }

    // ---- epilogue
    float alv = 0.f, om = 0.f;
    if (EP == 0) { alv = sigmoidf(*ra); om = __fsub_rn(1.0f, alv); }

    #pragma unroll
    for (int ma = 0; ma < 2; ma++) {
        #pragma unroll
        for (int na = 0; na < 4; na++) {
            const int r = bm + m0 + ma * 16 + g;
            const int c = bn + n0 + na * 8 + t * 2;
            const size_t i0 = (size_t)r * Nc + c;
            const size_t i1 = (size_t)(r + 8) * Nc + c;
            float v0 = d[ma][na][0], v1 = d[ma][na][1];
            float v2 = d[ma][na][2], v3 = d[ma][na][3];

            if (EP == 0) {
                float2 a0 = *reinterpret_cast<const float2*>(&Aecfp[i0]);
                float2 a1 = *reinterpret_cast<const float2*>(&Aecfp[i1]);
                float2 o0, o1;
                o0.x = __fadd_rn(__fmul_rn(alv, a0.x), __fmul_rn(om, fmaxf(v0, 0.0f)));
                o0.y = __fadd_rn(__fmul_rn(alv, a0.y), __fmul_rn(om, fmaxf(v1, 0.0f)));
                o1.x = __fadd_rn(__fmul_rn(alv, a1.x), __fmul_rn(om, fmaxf(v2, 0.0f)));
                o1.y = __fadd_rn(__fmul_rn(alv, a1.y), __fmul_rn(om, fmaxf(v3, 0.0f)));
                *reinterpret_cast<float2*>(&Cf[i0]) = o0;
                *reinterpret_cast<float2*>(&Cf[i1]) = o1;
            } else if (EP == 4) {
                write_split(Ch, Cl, i0, v0, v1);
                write_split(Ch, Cl, i1, v2, v3);
            } else {
                const float b0 = bias[c], b1 = bias[c + 1];
                if (EP == 3) {
                    float rs0 = 1.0f / fmaxf(rowsum[r], 1e-8f);
                    float rs1 = 1.0f / fmaxf(rowsum[r + 8], 1e-8f);
                    v0 *= rs0; v1 *= rs0; v2 *= rs1; v3 *= rs1;
                }
                v0 = geluf(v0 + b0); v1 = geluf(v1 + b1);
                v2 = geluf(v2 + b0); v3 = geluf(v3 + b1);
                if (EP == 3) {
                    float2 r0 = *reinterpret_cast<const float2*>(&resid[i0]);
                    float2 r1 = *reinterpret_cast<const float2*>(&resid[i1]);
                    v0 += r0.x; v1 += r0.y; v2 += r1.x; v3 += r1.y;
                }
                if (EP == 2) {
                    float2 o0 = {v0, v1}, o1 = {v2, v3};
                    *reinterpret_cast<float2*>(&Cf[i0]) = o0;
                    *reinterpret_cast<float2*>(&Cf[i1]) = o1;
                } else {
                    write_split(Ch, Cl, i0, v0, v1);
                    write_split(Ch, Cl, i1, v2, v3);
                }
            }
        }
    }
}

// ---------------- per-row top-K (threshold quick-reject, float4) ------------
__global__ void k_topk2(int rowOff)
{
    __shared__ ull cand[256 * KK];
    __shared__ ull red[256];

    const int row = blockIdx.x + rowOff;
    const int tid = threadIdx.x;
    const float4* src = reinterpret_cast<const float4*>(&g_Ab[(size_t)row * Nn]);

    ull loc[KK];
    float locv[KK];
    #pragma unroll
    for (int t = 0; t < KK; t++) { loc[t] = 0ULL; locv[t] = -1e30f; }
    float vth = -1e30f;

    for (int q = tid; q < Nn / 4; q += 256) {
        float4 v = src[q];
        float vv[4] = {v.x, v.y, v.z, v.w};
        #pragma unroll
        for (int e = 0; e < 4; e++) {
            float f = vv[e];
            if (f > vth) {
                int j = q * 4 + e;
                unsigned u = __float_as_uint(f);
                u ^= (u >> 31) ? 0xFFFFFFFFu : 0x80000000u;
                ull key = ((ull)u << 32) | (ull)(0xFFFFFFFFu - (unsigned)j);
                loc[KK - 1] = key; locv[KK - 1] = f;
                #pragma unroll
                for (int t = KK - 1; t > 0; t--) {
                    if (loc[t] > loc[t - 1]) {
                        ull tk = loc[t]; loc[t] = loc[t - 1]; loc[t - 1] = tk;
                        float tv = locv[t]; locv[t] = locv[t - 1]; locv[t - 1] = tv;
                    }
                }
                vth = locv[KK - 1];
            }
        }
    }
    #pragma unroll
    for (int t = 0; t < KK; t++) cand[tid * KK + t] = loc[t];
    __syncthreads();

    for (int t = 0; t < KK; t++) {
        ull m = 0ULL;
        for (int p = tid; p < 256 * KK; p += 256)
            if (cand[p] > m) m = cand[p];
        red[tid] = m;
        __syncthreads();
        for (int s = 128; s > 0; s >>= 1) {
            if (tid < s && red[tid + s] > red[tid]) red[tid] = red[tid + s];
            __syncthreads();
        }
        ull best = red[0];
        if (tid == 0)
            g_top[row * KK + t] = (int)(0xFFFFFFFFu - (unsigned)(best & 0xFFFFFFFFULL));
        for (int p = tid; p < 256 * KK; p += 256)
            if (cand[p] == best) cand[p] = 0ULL;
        __syncthreads();
    }
}

// ---------------- head tail ---------------------------------------------------
__global__ void k_head_tail(const float* __restrict__ wh, const float* __restrict__ bh,
                            float* __restrict__ out, int computeG,
                            const float* __restrict__ gam)
{
    __shared__ float swh[4 * H2s];
    for (int i = threadIdx.x; i < 4 * H2s; i += blockDim.x) {
        int c = i >> 8, d = i & 255;
        swh[i] = wh[d * 4 + c];
    }
    __syncthreads();

    const int warp = threadIdx.x >> 5;
    const int lane = threadIdx.x & 31;
    const int row = blockIdx.x * 8 + warp;

    float a0 = 0.f, a1 = 0.f, a2 = 0.f, a3 = 0.f;
    for (int d = lane; d < H2s; d += 32) {
        float v = g_L2[(size_t)row * H2s + d];
        a0 += v * swh[0 * H2s + d];
        a1 += v * swh[1 * H2s + d];
        a2 += v * swh[2 * H2s + d];
        a3 += v * swh[3 * H2s + d];
    }
    #pragma unroll
    for (int off = 16; off > 0; off >>= 1) {
        a0 += __shfl_xor_sync(0xffffffffu, a0, off);
        a1 += __shfl_xor_sync(0xffffffffu, a1, off);
        a2 += __shfl_xor_sync(0xffffffffu, a2, off);
        a3 += __shfl_xor_sync(0xffffffffu, a3, off);
    }
    if (lane == 0) {
        float r0 = a0 + bh[0], r1 = a1 + bh[1], r2 = a2 + bh[2], r3 = a3 + bh[3];
        float m  = r0;
        float vv = softplusf(r1) + 1e-6f;
        float aa = softplusf(r2) + 1.0f + 1e-6f;
        float bb = softplusf(r3) + 1e-6f;
        out[row]          = m;
        out[Nn + row]     = vv;
        out[2 * Nn + row] = aa;
        out[3 * Nn + row] = bb;
        if (computeG) {
            float u0 = bb / fmaxf(aa - 1.0f, 1e-8f);
            g_G[row] = 1.0f - (*gam) * sigmoidf(u0);
        }
    }
}

// ---------------- mask construction ------------------------------------------
__global__ void k_zero_mask()
{
    size_t idx = (size_t)blockIdx.x * blockDim.x + threadIdx.x;
    size_t total = (size_t)Nn * 256;
    size_t stride = (size_t)gridDim.x * blockDim.x;
    for (size_t p = idx; p < total; p += stride) g_mask[p] = 0u;
}

__global__ void k_set_mask()
{
    int e = blockIdx.x * blockDim.x + threadIdx.x;
    if (e >= Nn * KK) return;
    int i = e / KK;
    int j = g_top[e];
    if (j == i) return;
    atomicOr(&g_mask[i * 256 + (j >> 5)], 1u << (j & 31));
    atomicOr(&g_mask[j * 256 + (i >> 5)], 1u << (i & 31));
}

// ---------------- sparse per-row aggregation (writes Agg split) -------------
#define EB 2048
__global__ void k_edges(const float* __restrict__ X)
{
    __shared__ unsigned int mwords[256];
    __shared__ int sc[256];
    __shared__ int lst[EB];
    __shared__ float cf[EB];
    __shared__ float abv[EB];
    __shared__ float s_rowsum;

    const int row = blockIdx.x;
    const int tid = threadIdx.x;

    unsigned int w0 = g_mask[row * 256 + tid];
    mwords[tid] = w0;
    int myp = __popc(w0);
    sc[tid] = myp;
    __syncthreads();
    for (int off = 1; off < 256; off <<= 1) {
        int v = (tid >= off) ? sc[tid - off] : 0;
        __syncthreads();
        sc[tid] += v;
        __syncthreads();
    }
    const int myoff = sc[tid] - myp;
    const int E = sc[255];
    if (tid == 0) s_rowsum = 0.0f;
    __syncthreads();

    float racc0 = 0.f, racc1 = 0.f, racc2 = 0.f;

    for (int start = 0; start < E; start += EB) {
        int end = (E < start + EB) ? E : (start + EB);
        int cnt = end - start;
        {
            unsigned int w = mwords[tid];
            int pos = myoff;
            while (w) {
                int b = __ffs(w) - 1;
                w &= w - 1;
                if (pos >= start && pos < end) lst[pos - start] = tid * 32 + b;
                pos++;
            }
        }
        __syncthreads();
        for (int e = tid; e < cnt; e += 256) {
            int j = lst[e];
            float ab = g_Ab[(size_t)row * Nn + j];
            abv[e] = ab;
            cf[e] = ab * g_G[j];
        }
        __syncthreads();
        if (tid == 0) {
            float s = s_rowsum;
            for (int e = 0; e < cnt; e++) s += abv[e];
            s_rowsum = s;
        }
        for (int e = 0; e < cnt; e++) {
            float c = cf[e];
            const float* xr = &X[(size_t)lst[e] * Dd];
            racc0 += c * xr[tid];
            racc1 += c * xr[tid + 256];
            racc2 += c * xr[tid + 512];
        }
        __syncthreads();
    }

    const size_t b = (size_t)row * Dd;
    float vs[3] = {racc0, racc1, racc2};
    #pragma unroll
    for (int s = 0; s < 3; s++) {
        bf16 h = __float2bfloat16_rn(vs[s]);
        g_Aggh[b + tid + s * 256] = h;
        g_Aggl[b + tid + s * 256] = __float2bfloat16_rn(vs[s] - __bfloat162float(h));
    }
    if (tid == 0) g_rowsum[row] = s_rowsum;
}

// ---------------- launch ----------------------------------------------------
extern "C" void kernel_launch(void* const* d_in, const int* in_sizes, int n_in,
                              void* d_out, int out_size)
{
    const float* X     = (const float*)d_in[0];
    const float* A     = (const float*)d_in[1];
    const float* W_gm  = (const float*)d_in[2];
    const float* ra    = (const float*)d_in[3];
    const float* gam   = (const float*)d_in[4];
    const float* ih_w1 = (const float*)d_in[5];
    const float* ih_b1 = (const float*)d_in[6];
    const float* ih_w2 = (const float*)d_in[7];
    const float* ih_b2 = (const float*)d_in[8];
    const float* ih_wh = (const float*)d_in[9];
    const float* ih_bh = (const float*)d_in[10];
    const float* gcn_w = (const float*)d_in[11];
    const float* gcn_b = (const float*)d_in[12];
    const float* fh_w1 = (const float*)d_in[13];
    const float* fh_b1 = (const float*)d_in[14];
    const float* fh_w2 = (const float*)d_in[15];
    const float* fh_b2 = (const float*)d_in[16];
    const float* fh_wh = (const float*)d_in[17];
    const float* fh_bh = (const float*)d_in[18];
    float* out = (float*)d_out;

    static float *pAb = nullptr, *pL2 = nullptr, *pRs = nullptr;
    static bf16 *pXh, *pXl, *pYh, *pYl, *pL1h, *pL1l, *pXph, *pXpl, *pAggh, *pAggl;
    static bf16 *pWgmTh, *pWgmTl, *pW1aTh, *pW1aTl, *pW2aTh, *pW2aTl;
    static bf16 *pGcnTh, *pGcnTl, *pW1bTh, *pW1bTl, *pW2bTh, *pW2bTl;
    static cudaStream_t s2 = nullptr, s3 = nullptr;
    static cudaEvent_t evFork = nullptr, evJoin = nullptr, evS1 = nullptr, evTkLo = nullptr;
    if (!pAb) {
        cudaGetSymbolAddress((void**)&pAb, g_Ab);
        cudaGetSymbolAddress((void**)&pL2, g_L2);
        cudaGetSymbolAddress((void**)&pRs, g_rowsum);
        cudaGetSymbolAddress((void**)&pXh, g_Xh);   cudaGetSymbolAddress((void**)&pXl, g_Xl);
        cudaGetSymbolAddress((void**)&pYh, g_Yh);   cudaGetSymbolAddress((void**)&pYl, g_Yl);
        cudaGetSymbolAddress((void**)&pL1h, g_L1h); cudaGetSymbolAddress((void**)&pL1l, g_L1l);
        cudaGetSymbolAddress((void**)&pXph, g_Xph); cudaGetSymbolAddress((void**)&pXpl, g_Xpl);
        cudaGetSymbolAddress((void**)&pAggh, g_Aggh); cudaGetSymbolAddress((void**)&pAggl, g_Aggl);
        cudaGetSymbolAddress((void**)&pWgmTh, g_WgmTh); cudaGetSymbolAddress((void**)&pWgmTl, g_WgmTl);
        cudaGetSymbolAddress((void**)&pW1aTh, g_W1aTh); cudaGetSymbolAddress((void**)&pW1aTl, g_W1aTl);
        cudaGetSymbolAddress((void**)&pW2aTh, g_W2aTh); cudaGetSymbolAddress((void**)&pW2aTl, g_W2aTl);
        cudaGetSymbolAddress((void**)&pGcnTh, g_GcnTh); cudaGetSymbolAddress((void**)&pGcnTl, g_GcnTl);
        cudaGetSymbolAddress((void**)&pW1bTh, g_W1bTh); cudaGetSymbolAddress((void**)&pW1bTl, g_W1bTl);
        cudaGetSymbolAddress((void**)&pW2bTh, g_W2bTh); cudaGetSymbolAddress((void**)&pW2bTl, g_W2bTl);
        cudaFuncSetAttribute(k_hmma<0>, cudaFuncAttributeMaxDynamicSharedMemorySize, S_SMEM_BYTES);
        cudaFuncSetAttribute(k_hmma<1>, cudaFuncAttributeMaxDynamicSharedMemorySize, S_SMEM_BYTES);
        cudaFuncSetAttribute(k_hmma<2>, cudaFuncAttributeMaxDynamicSharedMemorySize, S_SMEM_BYTES);
        cudaFuncSetAttribute(k_hmma<3>, cudaFuncAttributeMaxDynamicSharedMemorySize, S_SMEM_BYTES);
        cudaFuncSetAttribute(k_hmma<4>, cudaFuncAttributeMaxDynamicSharedMemorySize, S_SMEM_BYTES);
        cudaStreamCreateWithFlags(&s2, cudaStreamNonBlocking);
        cudaStreamCreateWithFlags(&s3, cudaStreamNonBlocking);
        cudaEventCreateWithFlags(&evFork, cudaEventDisableTiming);
        cudaEventCreateWithFlags(&evJoin, cudaEventDisableTiming);
        cudaEventCreateWithFlags(&evS1, cudaEventDisableTiming);
        cudaEventCreateWithFlags(&evTkLo, cudaEventDisableTiming);
    }

    dim3 blk(256);
    dim3 blkG(GT);
    dim3 tsb(32, 8);
    cudaStream_t s0 = 0;   // legacy default (captured)

    // ---- main path (s0): X split
    k_split<<<2048, blk, 0, s0>>>(X, pXh, pXl, (size_t)Nn * Dd);
    cudaEventRecord(evFork, s0);

    // ---- side path (s2): head-1 chain + remaining weight tsplits
    cudaStreamWaitEvent(s2, evFork, 0);
    k_tsplit<<<dim3(H1s / 32, Dd / 32), tsb, 0, s2>>>(ih_w1, pW1aTh, pW1aTl, Dd, H1s);
    k_tsplit<<<dim3(H2s / 32, H1s / 32), tsb, 0, s2>>>(ih_w2, pW2aTh, pW2aTl, H1s, H2s);
    k_tsplit<<<dim3(Dd / 32, Dd / 32), tsb, 0, s2>>>(gcn_w, pGcnTh, pGcnTl, Dd, Dd);
    k_tsplit<<<dim3(H1s / 32, Dd / 32), tsb, 0, s2>>>(fh_w1, pW1bTh, pW1bTl, Dd, H1s);
    k_tsplit<<<dim3(H2s / 32, H1s / 32), tsb, 0, s2>>>(fh_w2, pW2bTh, pW2bTl, H1s, H2s);
    k_hmma<1><<<dim3(H1s / 128, Nn / 128), blkG, S_SMEM_BYTES, s2>>>(
        pXh, pXl, pW1aTh, pW1aTl, nullptr, pL1h, pL1l, H1s, Dd, 0,
        ih_b1, nullptr, nullptr, nullptr, nullptr);
    k_hmma<2><<<dim3(H2s / 128, Nn / 128), blkG, S_SMEM_BYTES, s2>>>(
        pL1h, pL1l, pW2aTh, pW2aTl, pL2, nullptr, nullptr, H2s, H1s, 0,
        ih_b2, nullptr, nullptr, nullptr, nullptr);
    k_head_tail<<<Nn / 8, blk, 0, s2>>>(ih_wh, ih_bh, out, 1, gam);
    cudaEventRecord(evJoin, s2);

    // ---- topk stream (s3): zero mask early (no deps)
    k_zero_mask<<<2048, blk, 0, s3>>>();

    // ---- main path continues (s0)
    k_tsplit<<<dim3(Dd / 32, Dd / 32), tsb, 0, s0>>>(W_gm, pWgmTh, pWgmTl, Dd, Dd);
    k_hmma<4><<<dim3(Dd / 128, Nn / 128), blkG, S_SMEM_BYTES, s0>>>(
        pXh, pXl, pWgmTh, pWgmTl, nullptr, pYh, pYl, Dd, Dd, 0,
        nullptr, nullptr, nullptr, nullptr, nullptr);
    // S lower row-half: rows [0, 4096)
    k_hmma<0><<<dim3(Nn / 128, Nn / 256), blkG, S_SMEM_BYTES, s0>>>(
        pYh, pYl, pXh, pXl, pAb, nullptr, nullptr, Nn, Dd, 0,
        nullptr, nullptr, nullptr, A, ra);
    cudaEventRecord(evS1, s0);
    // S upper row-half: rows [4096, 8192)
    k_hmma<0><<<dim3(Nn / 128, Nn / 256), blkG, S_SMEM_BYTES, s0>>>(
        pYh, pYl, pXh, pXl, pAb, nullptr, nullptr, Nn, Dd, Nn / 256,
        nullptr, nullptr, nullptr, A, ra);

    // topk lower half overlaps S upper half (s3)
    cudaStreamWaitEvent(s3, evS1, 0);
    k_topk2<<<Nn / 2, blk, 0, s3>>>(0);
    cudaEventRecord(evTkLo, s3);

    // topk upper half on s0, then set_mask after both halves
    k_topk2<<<Nn / 2, blk, 0, s0>>>(Nn / 2);
    cudaStreamWaitEvent(s0, evTkLo, 0);
    k_set_mask<<<(Nn * KK + 255) / 256, blk, 0, s0>>>();

    // ---- join: edges needs G (s2) + mask + Ab (s0)
    cudaStreamWaitEvent(s0, evJoin, 0);
    k_edges<<<Nn, blk, 0, s0>>>(X);

    // Xp = X + gelu((Agg/rowsum) @ gcn_w + gcn_b)  (EP3 -> split)
    k_hmma<3><<<dim3(Dd / 128, Nn / 128), blkG, S_SMEM_BYTES, s0>>>(
        pAggh, pAggl, pGcnTh, pGcnTl, nullptr, pXph, pXpl, Dd, Dd, 0,
        gcn_b, pRs, X, nullptr, nullptr);

    // NIG head 2
    k_hmma<1><<<dim3(H1s / 128, Nn / 128), blkG, S_SMEM_BYTES, s0>>>(
        pXph, pXpl, pW1bTh, pW1bTl, nullptr, pL1h, pL1l, H1s, Dd, 0,
        fh_b1, nullptr, nullptr, nullptr, nullptr);
    k_hmma<2><<<dim3(H2s / 128, Nn / 128), blkG, S_SMEM_BYTES, s0>>>(
        pL1h, pL1l, pW2bTh, pW2bTl, pL2, nullptr, nullptr, H2s, H1s, 0,
        fh_b2, nullptr, nullptr, nullptr, nullptr);
    k_head_tail<<<Nn / 8, blk, 0, s0>>>(fh_wh, fh_bh, out + 4 * Nn, 0, nullptr);
}